// round 9
// baseline (speedup 1.0000x reference)
#include <cuda_runtime.h>

#define H      768
#define DD     192
#define WIN    960          // H + DD
#define NCOMBO (8 * 17)
#define SEQ    2048
#define LN_EPS 1e-12f
#define TOK_PER_BLK 16

#define KC      64          // K-chunk
#define KC4     16          // KC/4
#define NK_TOK  12          // 768 / 64
#define NK_DIN  3           // 192 / 64
#define NCT     24          // 768 channels / 32 per tile
#define SWP     33          // padded pitch for transposed W tile

#define NB_TOK  (NK_TOK * NCT)            // 288
#define NB_DIN  (NK_DIN * NCT)            // 72
#define NB_GEMM (NB_TOK + NB_DIN)         // 360
#define NB_COMBO 64                       // 64 blocks x 256 thr x 4 tok = 65536

// Scratch (no cudaMalloc allowed)
__device__ float g_ptok[NK_TOK * 8 * H];
__device__ float g_pdin[NK_DIN * 16 * H];
__device__ float g_table[NCOMBO * H];
__device__ uint4 g_combo4[4096];          // 65536 uint8 combos, 16B-aligned

// ---------------------------------------------------------------------------
// Kernel 1 (v7): K-split GEMM, warp-per-K-octet, + combo precompute blocks.
// Blocks 0..287   : token part (kc<12, ct<24). 32 ch x 8 rows.
// Blocks 288..359 : dinuc part (kc<3).         32 ch x 16 rows.
// Blocks 360..423 : combo precompute (independent of GEMM).
// GEMM compute: warp kq owns k in [kq*8, kq*8+8); lane = channel. Per k:
//   1 conflict-free W LDS + broadcast float4 reads of transposed E ->
//   8/16 register accumulators. Cross-kq combine via smem (no shuffles).
// ---------------------------------------------------------------------------
__global__ __launch_bounds__(256) void partial_kernel(
    const int*   __restrict__ ids32,
    const float* __restrict__ tok_emb,   // [8, 768]
    const float* __restrict__ din_emb,   // [16, 192]
    const float* __restrict__ W,         // [768, 960] row-major
    int n_tokens)
{
    __shared__ float smem_buf[7232];     // 28.9 KB, carved below

    const int tid = threadIdx.x;

    // ================= combo precompute =================
    if (blockIdx.x >= NB_GEMM) {
        __shared__ int s_is64;
        if (tid == 0) {
            int ok = 1;
            #pragma unroll 8
            for (int i = 0; i < 64; i++)
                if (ids32[2 * i + 1] != 0) ok = 0;
            s_is64 = ok;
        }
        __syncthreads();
        const int stride = s_is64 ? 2 : 1;

        const int cb   = blockIdx.x - NB_GEMM;
        const int base = cb * 1024 + tid * 4;
        uchar4 c4;
        unsigned char cc[4];
        #pragma unroll
        for (int j = 0; j < 4; j++) {
            const int t = base + j;
            int combo = 0;
            if (t < n_tokens) {
                const int a = __ldg(&ids32[t * stride]);
                const int s = t & (SEQ - 1);
                if (s == SEQ - 1) {
                    combo = a * 17 + 16;
                } else {
                    const int nx = __ldg(&ids32[(t + 1) * stride]);
                    const int dd = (a >= 4 && nx >= 4) ? ((a - 4) * 4 + (nx - 4)) : 0;
                    combo = a * 17 + dd;
                }
            }
            cc[j] = (unsigned char)combo;
        }
        c4.x = cc[0]; c4.y = cc[1]; c4.z = cc[2]; c4.w = cc[3];
        reinterpret_cast<uchar4*>(g_combo4)[cb * 256 + tid] = c4;
        return;
    }

    // ================= GEMM blocks =================
    const int ch = tid & 31;
    const int kq = tid >> 5;
    const float4* W4 = reinterpret_cast<const float4*>(W);

    if (blockIdx.x < NB_TOK) {
        // ---------- token part ----------
        const int kc = blockIdx.x / NCT;      // 0..11
        const int ct = blockIdx.x % NCT;      // 0..23

        float* sW   = smem_buf;                // KC*SWP   = 2112 floats
        float* sET  = smem_buf + 2112;         // 64 k x 8 rows = 512 floats
        float* sAcc = smem_buf + 2112 + 512;   // 8 kq x 256 = 2048 floats

        // stage W transposed: 32 ch x 16 float4 = 512 float4, 2/thread
        #pragma unroll
        for (int t = 0; t < 2; t++) {
            const int idx = t * 256 + tid;
            const int c   = idx / KC4;
            const int k4  = idx % KC4;
            const float4 w = __ldg(&W4[(size_t)(ct * 32 + c) * (WIN / 4) + kc * KC4 + k4]);
            float* dst = &sW[(k4 * 4) * SWP + c];
            dst[0 * SWP] = w.x; dst[1 * SWP] = w.y; dst[2 * SWP] = w.z; dst[3 * SWP] = w.w;
        }
        // stage E transposed: 8 rows x 16 float4; sET[k*8 + row]
        if (tid < 128) {
            const int row = tid >> 4;
            const int k4  = tid & 15;
            const float4 e = __ldg(&reinterpret_cast<const float4*>(tok_emb)[row * (H / 4) + kc * KC4 + k4]);
            sET[(k4 * 4 + 0) * 8 + row] = e.x;
            sET[(k4 * 4 + 1) * 8 + row] = e.y;
            sET[(k4 * 4 + 2) * 8 + row] = e.z;
            sET[(k4 * 4 + 3) * 8 + row] = e.w;
        }
        __syncthreads();

        float acc[8];
        #pragma unroll
        for (int r = 0; r < 8; r++) acc[r] = 0.f;

        #pragma unroll
        for (int kk = 0; kk < 8; kk++) {
            const int k = kq * 8 + kk;
            const float wv = sW[k * SWP + ch];
            const float4 e0 = *reinterpret_cast<const float4*>(&sET[k * 8]);
            const float4 e1 = *reinterpret_cast<const float4*>(&sET[k * 8 + 4]);
            acc[0] += wv * e0.x; acc[1] += wv * e0.y; acc[2] += wv * e0.z; acc[3] += wv * e0.w;
            acc[4] += wv * e1.x; acc[5] += wv * e1.y; acc[6] += wv * e1.z; acc[7] += wv * e1.w;
        }
        #pragma unroll
        for (int r = 0; r < 8; r++) sAcc[kq * 256 + r * 32 + ch] = acc[r];
        __syncthreads();

        // final combine: thread tid -> output (r = tid>>5, ch = tid&31)
        {
            float v = 0.f;
            #pragma unroll
            for (int q = 0; q < 8; q++) v += sAcc[q * 256 + tid];
            const int r = tid >> 5;
            g_ptok[(kc * 8 + r) * H + ct * 32 + (tid & 31)] = v;
        }
    } else {
        // ---------- dinuc part ----------
        const int b2 = blockIdx.x - NB_TOK;
        const int kc = b2 / NCT;              // 0..2
        const int ct = b2 % NCT;

        float* sW   = smem_buf;                // 2112 floats
        float* sET  = smem_buf + 2112;         // 64 k x 16 rows = 1024 floats
        float* sAcc = smem_buf + 2112 + 1024;  // 8 kq x 512 = 4096 floats

        #pragma unroll
        for (int t = 0; t < 2; t++) {
            const int idx = t * 256 + tid;
            const int c   = idx / KC4;
            const int k4  = idx % KC4;
            const float4 w = __ldg(&W4[(size_t)(ct * 32 + c) * (WIN / 4) + (H / 4) + kc * KC4 + k4]);
            float* dst = &sW[(k4 * 4) * SWP + c];
            dst[0 * SWP] = w.x; dst[1 * SWP] = w.y; dst[2 * SWP] = w.z; dst[3 * SWP] = w.w;
        }
        // stage E transposed: 16 rows x 16 float4; sET[k*16 + row]
        {
            const int row = tid >> 4;
            const int k4  = tid & 15;
            const float4 e = __ldg(&reinterpret_cast<const float4*>(din_emb)[row * (DD / 4) + kc * KC4 + k4]);
            sET[(k4 * 4 + 0) * 16 + row] = e.x;
            sET[(k4 * 4 + 1) * 16 + row] = e.y;
            sET[(k4 * 4 + 2) * 16 + row] = e.z;
            sET[(k4 * 4 + 3) * 16 + row] = e.w;
        }
        __syncthreads();

        float acc[16];
        #pragma unroll
        for (int r = 0; r < 16; r++) acc[r] = 0.f;

        #pragma unroll
        for (int kk = 0; kk < 8; kk++) {
            const int k = kq * 8 + kk;
            const float wv = sW[k * SWP + ch];
            #pragma unroll
            for (int p = 0; p < 4; p++) {
                const float4 e = *reinterpret_cast<const float4*>(&sET[k * 16 + p * 4]);
                acc[p * 4 + 0] += wv * e.x; acc[p * 4 + 1] += wv * e.y;
                acc[p * 4 + 2] += wv * e.z; acc[p * 4 + 3] += wv * e.w;
            }
        }
        #pragma unroll
        for (int r = 0; r < 16; r++) sAcc[kq * 512 + r * 32 + ch] = acc[r];
        __syncthreads();

        // 512 outputs, 2 per thread
        #pragma unroll
        for (int h = 0; h < 2; h++) {
            const int out = h * 256 + tid;
            float v = 0.f;
            #pragma unroll
            for (int q = 0; q < 8; q++) v += sAcc[q * 512 + out];
            const int r = out >> 5;
            g_pdin[(kc * 16 + r) * H + ct * 32 + (out & 31)] = v;
        }
    }
}

// ---------------------------------------------------------------------------
// Kernel 2: sum K-partials, then two-pass LayerNorm into the 136-row table.
// ---------------------------------------------------------------------------
__global__ __launch_bounds__(H) void table_kernel(
    const float* __restrict__ bias,
    const float* __restrict__ gamma,
    const float* __restrict__ beta)
{
    const int o    = threadIdx.x;
    const int a    = blockIdx.x / 17;
    const int d    = blockIdx.x % 17;
    const int lane = o & 31;
    const int warp = o >> 5;

    float x = bias[o];
    #pragma unroll
    for (int kc = 0; kc < NK_TOK; kc++) x += g_ptok[(kc * 8 + a) * H + o];
    if (d < 16) {
        #pragma unroll
        for (int kc = 0; kc < NK_DIN; kc++) x += g_pdin[(kc * 16 + d) * H + o];
    }

    __shared__ float sred[32];
    __shared__ float s_mu, s_var;

    float v = x;
    #pragma unroll
    for (int off = 16; off > 0; off >>= 1) v += __shfl_down_sync(0xffffffffu, v, off);
    if (lane == 0) sred[warp] = v;
    __syncthreads();
    if (o < 32) {
        float t = (o < (H / 32)) ? sred[o] : 0.f;
        #pragma unroll
        for (int off = 16; off > 0; off >>= 1) t += __shfl_down_sync(0xffffffffu, t, off);
        if (o == 0) s_mu = t * (1.0f / H);
    }
    __syncthreads();

    const float dx = x - s_mu;
    v = dx * dx;
    #pragma unroll
    for (int off = 16; off > 0; off >>= 1) v += __shfl_down_sync(0xffffffffu, v, off);
    if (lane == 0) sred[warp] = v;
    __syncthreads();
    if (o < 32) {
        float t = (o < (H / 32)) ? sred[o] : 0.f;
        #pragma unroll
        for (int off = 16; off > 0; off >>= 1) t += __shfl_down_sync(0xffffffffu, t, off);
        if (o == 0) s_var = t * (1.0f / H);
    }
    __syncthreads();

    const float inv = rsqrtf(s_var + LN_EPS);
    g_table[blockIdx.x * H + o] = dx * inv * gamma[o] + beta[o];
}

// ---------------------------------------------------------------------------
// Kernel 3: gather v3 — barrier-free. One broadcast uint4 __ldg fetches the
// block's 16 combos; 192 threads stream 16 rows with full store MLP.
// ---------------------------------------------------------------------------
__global__ __launch_bounds__(192) void gather_kernel(
    float* __restrict__ out)
{
    const int tid = threadIdx.x;
    const uint4 c16 = __ldg(&g_combo4[blockIdx.x]);

    unsigned char cc[16];
    *reinterpret_cast<uint4*>(cc) = c16;

    const float4* tab4 = reinterpret_cast<const float4*>(g_table);
    float4* out4 = reinterpret_cast<float4*>(out)
                 + (size_t)blockIdx.x * TOK_PER_BLK * (H / 4) + tid;

    #pragma unroll
    for (int i = 0; i < TOK_PER_BLK; i++) {
        const float4 v = __ldg(&tab4[(int)cc[i] * (H / 4) + tid]);
        __stcs(out4, v);
        out4 += (H / 4);
    }
}

// ---------------------------------------------------------------------------
extern "C" void kernel_launch(void* const* d_in, const int* in_sizes, int n_in,
                              void* d_out, int out_size) {
    const int*   ids32   = (const int*)d_in[0];
    const float* tok_emb = (const float*)d_in[1];
    const float* din_emb = (const float*)d_in[2];
    const float* W       = (const float*)d_in[3];
    const float* bias    = (const float*)d_in[4];
    const float* gamma   = (const float*)d_in[5];
    const float* beta    = (const float*)d_in[6];
    float*       out     = (float*)d_out;

    const int n_tokens = in_sizes[0];                       // 65536
    const int nblk     = (n_tokens + TOK_PER_BLK - 1) / TOK_PER_BLK;

    partial_kernel<<<NB_GEMM + NB_COMBO, 256>>>(ids32, tok_emb, din_emb, W, n_tokens);
    table_kernel<<<NCOMBO, H>>>(bias, gamma, beta);
    gather_kernel<<<nblk, 192>>>(out);
}